// round 9
// baseline (speedup 1.0000x reference)
#include <cuda_runtime.h>
#include <math.h>

// ---------------------------------------------------------------------------
// MyDetector: YOLO-style decode + threshold + top-300 + greedy NMS
// SINGLE fused kernel: one CTA per image does scan -> decode -> sort -> NMS
// -> emit entirely in shared memory. No global scratch, no extra launches.
//
// Inputs (metadata order):
//   d_in[0] out13 (N,255,13,13) f32   d_in[3] anchors13 (3,2)
//   d_in[1] out26 (N,255,26,26) f32   d_in[4] anchors26 (3,2)
//   d_in[2] out52 (N,255,52,52) f32   d_in[5] anchors52 (3,2)
//                                      d_in[6] thresh scalar
// Output: (N,300,7) f32  rows = [conf, ox, oy, w, h, cls, n] * keep
//
// Only boxes with conf > thresh survive the keep mask; ~66/image with these
// inputs. Conf ties are real (quantized normals) and broken exactly like
// jax.lax.top_k: by original flat index ascending, where flat index =
// scale_offset + (y*W+x)*3 + a  (anchor innermost).
// ---------------------------------------------------------------------------

#define HW13 169
#define HW26 676
#define HW52 2704
#define NB13 (3 * HW13)                  // 507
#define NB26 (3 * HW26)                  // 2028
#define NB52 (3 * HW52)                  // 8112
#define NBOX (NB13 + NB26 + NB52)        // 10647
#define CAP   512                        // per-image survivor cap (mean ~66, >50 sigma)
#define KDET  300
#define NTHR  1024

__global__ __launch_bounds__(NTHR, 1)
void detector_fused_kernel(const float* __restrict__ o13,
                           const float* __restrict__ o26,
                           const float* __restrict__ o52,
                           const float* __restrict__ a13,
                           const float* __restrict__ a26,
                           const float* __restrict__ a52,
                           const float* __restrict__ tptr,
                           float* __restrict__ out)
{
    // Unsorted survivor pool
    __shared__ float s_conf[CAP];
    __shared__ float s_ox[CAP], s_oy[CAP], s_w[CAP], s_h[CAP], s_cls[CAP];
    __shared__ int   s_origi[CAP];
    __shared__ int   s_cnt;
    // Sorted (top-k order) arrays
    __shared__ float s_box[KDET][6];
    __shared__ float s_cor[KDET][4];
    __shared__ float s_area[KDET];
    __shared__ int   s_keep[KDET];

    const int n   = blockIdx.x;
    const int tid = threadIdx.x;

    if (tid == 0) s_cnt = 0;
    __syncthreads();

    const float thr = *tptr;

    // ---- Phase 1: scan all 10647 boxes, decode survivors into shared ----
    for (int t = tid; t < NBOX; t += NTHR) {
        const float* src;
        const float* anc;
        float stride;
        int HW, W, u, off;

        if (t < NB13)             { src = o13; anc = a13; stride = 32.0f; HW = HW13; W = 13; u = t;               off = 0; }
        else if (t < NB13 + NB26) { src = o26; anc = a26; stride = 16.0f; HW = HW26; W = 26; u = t - NB13;        off = NB13; }
        else                      { src = o52; anc = a52; stride =  8.0f; HW = HW52; W = 52; u = t - NB13 - NB26; off = NB13 + NB26; }

        int a    = u / HW;        // anchor 0..2
        int cell = u - a * HW;    // y*W + x : consecutive threads -> consecutive cells (coalesced)

        const float* base = src + ((long)n * 255 + (long)a * 85) * HW + cell;

        float conf = base[0];
        if (!(conf > thr)) continue;

        float tx = base[(long)1 * HW];
        float ty = base[(long)2 * HW];
        float tw = base[(long)3 * HW];
        float th = base[(long)4 * HW];

        // argmax over 80 classes, first-occurrence tie-break (strict >)
        int   best = 0;
        float bv   = base[(long)5 * HW];
        #pragma unroll 8
        for (int f = 1; f < 80; ++f) {
            float v = base[(long)(5 + f) * HW];
            if (v > bv) { bv = v; best = f; }
        }

        int x = cell % W;
        int y = cell / W;

        int slot = atomicAdd(&s_cnt, 1);
        if (slot < CAP) {
            s_conf[slot]  = conf;
            s_ox[slot]    = ((float)x + tx) * stride;
            s_oy[slot]    = ((float)y + ty) * stride;
            s_w[slot]     = expf(tw) * anc[2 * a + 0];
            s_h[slot]     = expf(th) * anc[2 * a + 1];
            s_cls[slot]   = (float)best;
            s_origi[slot] = off + cell * 3 + a;   // reference flat index (anchor innermost)
        }
    }
    __syncthreads();

    int V = s_cnt;
    if (V > CAP) V = CAP;
    const int M = (V < KDET) ? V : KDET;

    // ---- Phase 2: O(V^2) rank sort by (conf desc, orig asc) == top_k order ----
    for (int i = tid; i < V; i += NTHR) {
        float si = s_conf[i];
        int   oi = s_origi[i];
        int   rank = 0;
        for (int j = 0; j < V; ++j) {
            float sj = s_conf[j];
            rank += (sj > si) || (sj == si && s_origi[j] < oi);
        }
        if (rank < KDET) {
            float ox = s_ox[i], oy = s_oy[i], w = s_w[i], h = s_h[i];
            s_box[rank][0] = si;
            s_box[rank][1] = ox;
            s_box[rank][2] = oy;
            s_box[rank][3] = w;
            s_box[rank][4] = h;
            s_box[rank][5] = s_cls[i];
            float x1 = ox - w * 0.5f, y1 = oy - h * 0.5f;
            float x2 = ox + w * 0.5f, y2 = oy + h * 0.5f;
            s_cor[rank][0] = x1; s_cor[rank][1] = y1;
            s_cor[rank][2] = x2; s_cor[rank][3] = y2;
            s_area[rank]   = (x2 - x1) * (y2 - y1);
        }
    }
    __syncthreads();

    // ---- Phase 3: greedy NMS on warp 0 (sequential i, warp-parallel j<i) ----
    if (tid < 32) {
        for (int i = 0; i < M; ++i) {
            float xi1 = s_cor[i][0], yi1 = s_cor[i][1];
            float xi2 = s_cor[i][2], yi2 = s_cor[i][3];
            float ai  = s_area[i];
            float ci  = s_box[i][5];
            bool  sup = false;
            for (int j = tid; j < i; j += 32) {
                if (s_keep[j] && s_box[j][5] == ci) {
                    float ix1 = fmaxf(xi1, s_cor[j][0]);
                    float iy1 = fmaxf(yi1, s_cor[j][1]);
                    float ix2 = fminf(xi2, s_cor[j][2]);
                    float iy2 = fminf(yi2, s_cor[j][3]);
                    float iw = ix2 - ix1; if (iw < 0.0f) iw = 0.0f;
                    float ih = iy2 - iy1; if (ih < 0.0f) ih = 0.0f;
                    float inter = iw * ih;
                    float uni   = ai + s_area[j] - inter;
                    if (inter / fmaxf(uni, 1e-9f) > 0.3f) sup = true;
                }
            }
            sup = __any_sync(0xffffffffu, sup);
            if (tid == 0) s_keep[i] = sup ? 0 : 1;
            __syncwarp();
        }
    }
    __syncthreads();

    // ---- Phase 4: emit all 300 rows (zeros for empty/suppressed slots) ----
    float* po = out + (long)n * KDET * 7;
    for (int r = tid; r < KDET; r += NTHR) {
        float v0 = 0.f, v1 = 0.f, v2 = 0.f, v3 = 0.f, v4 = 0.f, v5 = 0.f, v6 = 0.f;
        if (r < M && s_keep[r]) {
            v0 = s_box[r][0]; v1 = s_box[r][1]; v2 = s_box[r][2];
            v3 = s_box[r][3]; v4 = s_box[r][4]; v5 = s_box[r][5];
            v6 = (float)n;
        }
        float* pr = po + (long)r * 7;
        pr[0] = v0; pr[1] = v1; pr[2] = v2; pr[3] = v3;
        pr[4] = v4; pr[5] = v5; pr[6] = v6;
    }
}

extern "C" void kernel_launch(void* const* d_in, const int* in_sizes, int n_in,
                              void* d_out, int out_size)
{
    const float* o13 = (const float*)d_in[0];
    const float* o26 = (const float*)d_in[1];
    const float* o52 = (const float*)d_in[2];
    const float* a13 = (const float*)d_in[3];
    const float* a26 = (const float*)d_in[4];
    const float* a52 = (const float*)d_in[5];
    const float* thr = (const float*)d_in[6];

    int N = in_sizes[0] / (255 * HW13);

    detector_fused_kernel<<<N, NTHR>>>(o13, o26, o52, a13, a26, a52, thr,
                                       (float*)d_out);
}

// round 12
// speedup vs baseline: 1.6946x; 1.6946x over previous
#include <cuda_runtime.h>
#include <math.h>

// ---------------------------------------------------------------------------
// MyDetector: YOLO-style decode + threshold + top-300 + greedy NMS
// Single fused kernel, one CTA per image:
//   P1 batched coalesced conf scan -> candidate index list (shared)
//   P2 warp-per-survivor decode (32 lanes split the 80-class argmax)
//   P3 rank sort by (conf desc, orig asc)  == jax.lax.top_k order
//   P4 parallel suppression-bitmask build (row per thread, no atomics)
//   P5 sequential greedy scan on 64-bit masks (1 thread, ~66 iters)
//   P6 emit 300 rows
// ---------------------------------------------------------------------------

#define HW13 169
#define HW26 676
#define HW52 2704
#define NB13 (3 * HW13)                  // 507
#define NB26 (3 * HW26)                  // 2028
#define NB52 (3 * HW52)                  // 8112
#define NBOX (NB13 + NB26 + NB52)        // 10647
#define CAP   512
#define KDET  300
#define NTHR  1024
#define NITER ((NBOX + NTHR - 1) / NTHR) // 11
#define NWRD  ((KDET + 63) / 64)         // 5

struct ScaleInfo {
    const float* src; const float* anc;
    float stride; int HW, W, u, off;
};

__device__ __forceinline__ ScaleInfo scale_of(int t,
    const float* o13, const float* o26, const float* o52,
    const float* a13, const float* a26, const float* a52)
{
    ScaleInfo s;
    if (t < NB13)             { s.src=o13; s.anc=a13; s.stride=32.f; s.HW=HW13; s.W=13; s.u=t;             s.off=0; }
    else if (t < NB13+NB26)   { s.src=o26; s.anc=a26; s.stride=16.f; s.HW=HW26; s.W=26; s.u=t-NB13;        s.off=NB13; }
    else                      { s.src=o52; s.anc=a52; s.stride= 8.f; s.HW=HW52; s.W=52; s.u=t-NB13-NB26;   s.off=NB13+NB26; }
    return s;
}

__global__ __launch_bounds__(NTHR, 1)
void detector_fused_kernel(const float* __restrict__ o13,
                           const float* __restrict__ o26,
                           const float* __restrict__ o52,
                           const float* __restrict__ a13,
                           const float* __restrict__ a26,
                           const float* __restrict__ a52,
                           const float* __restrict__ tptr,
                           float* __restrict__ out)
{
    __shared__ int   s_candt[CAP];
    __shared__ float s_conf[CAP];
    __shared__ float s_ox[CAP], s_oy[CAP], s_w[CAP], s_h[CAP], s_cls[CAP];
    __shared__ int   s_origi[CAP];
    __shared__ int   s_cnt;
    __shared__ float s_box[KDET][6];
    __shared__ float s_cor[KDET][4];
    __shared__ float s_area[KDET];
    __shared__ int   s_keep[KDET];
    __shared__ unsigned long long s_sup[KDET][NWRD];

    const long n   = blockIdx.x;
    const int  tid = threadIdx.x;
    const int  wid = tid >> 5;
    const int  lane = tid & 31;

    if (tid == 0) s_cnt = 0;
    __syncthreads();

    const float thr = *tptr;

    // ---- P1: batched conf scan (11 independent loads -> MLP=11) ----
    float cv[NITER];
    #pragma unroll
    for (int k = 0; k < NITER; ++k) {
        int t = tid + k * NTHR;
        cv[k] = -1e30f;
        if (t < NBOX) {
            ScaleInfo s = scale_of(t, o13, o26, o52, a13, a26, a52);
            int a    = s.u / s.HW;
            int cell = s.u - a * s.HW;   // consecutive tid -> consecutive cells: coalesced
            cv[k] = s.src[(n * 255 + (long)a * 85) * s.HW + cell];
        }
    }
    #pragma unroll
    for (int k = 0; k < NITER; ++k) {
        if (cv[k] > thr) {
            int slot = atomicAdd(&s_cnt, 1);
            if (slot < CAP) { s_candt[slot] = tid + k * NTHR; s_conf[slot] = cv[k]; }
        }
    }
    __syncthreads();

    int V = s_cnt;
    if (V > CAP) V = CAP;
    const int M = (V < KDET) ? V : KDET;

    // ---- P2: warp-per-survivor decode + 80-class argmax ----
    for (int c = wid; c < V; c += (NTHR / 32)) {
        int t = s_candt[c];
        ScaleInfo s = scale_of(t, o13, o26, o52, a13, a26, a52);
        int a    = s.u / s.HW;
        int cell = s.u - a * s.HW;
        const float* base = s.src + (n * 255 + (long)a * 85) * s.HW + cell;

        // lanes split 80 classes: lane, lane+32, lane+64(<80); lanes 0-3 also fetch coords
        float v0 = base[(long)(5 + lane) * s.HW];
        float v1 = base[(long)(5 + 32 + lane) * s.HW];
        float v2 = (lane < 16) ? base[(long)(5 + 64 + lane) * s.HW] : -1e30f;
        float coord = (lane < 4) ? base[(long)(1 + lane) * s.HW] : 0.0f;

        float bv = v0; int bi = lane;
        if (v1 > bv) { bv = v1; bi = lane + 32; }
        if (lane < 16 && v2 > bv) { bv = v2; bi = lane + 64; }
        #pragma unroll
        for (int o = 16; o > 0; o >>= 1) {
            float ov = __shfl_down_sync(0xffffffffu, bv, o);
            int   oi = __shfl_down_sync(0xffffffffu, bi, o);
            if (ov > bv || (ov == bv && oi < bi)) { bv = ov; bi = oi; }
        }
        float tx = __shfl_sync(0xffffffffu, coord, 0);
        float ty = __shfl_sync(0xffffffffu, coord, 1);
        float tw = __shfl_sync(0xffffffffu, coord, 2);
        float th = __shfl_sync(0xffffffffu, coord, 3);

        if (lane == 0) {
            int x = cell % s.W, y = cell / s.W;
            s_ox[c]    = ((float)x + tx) * s.stride;
            s_oy[c]    = ((float)y + ty) * s.stride;
            s_w[c]     = expf(tw) * s.anc[2 * a + 0];
            s_h[c]     = expf(th) * s.anc[2 * a + 1];
            s_cls[c]   = (float)bi;
            s_origi[c] = s.off + cell * 3 + a;   // reference flat index (anchor innermost)
        }
    }
    __syncthreads();

    // ---- P3: rank sort by (conf desc, orig asc) ----
    for (int i = tid; i < V; i += NTHR) {
        float si = s_conf[i];
        int   oi = s_origi[i];
        int   rank = 0;
        for (int j = 0; j < V; ++j) {
            float sj = s_conf[j];
            rank += (sj > si) || (sj == si && s_origi[j] < oi);
        }
        if (rank < KDET) {
            float ox = s_ox[i], oy = s_oy[i], w = s_w[i], h = s_h[i];
            s_box[rank][0] = si;  s_box[rank][1] = ox; s_box[rank][2] = oy;
            s_box[rank][3] = w;   s_box[rank][4] = h;  s_box[rank][5] = s_cls[i];
            float x1 = ox - w * 0.5f, y1 = oy - h * 0.5f;
            float x2 = ox + w * 0.5f, y2 = oy + h * 0.5f;
            s_cor[rank][0] = x1; s_cor[rank][1] = y1;
            s_cor[rank][2] = x2; s_cor[rank][3] = y2;
            s_area[rank]   = (x2 - x1) * (y2 - y1);
        }
    }
    __syncthreads();

    // ---- P4: suppression bitmasks, one row per thread (j < i only) ----
    for (int i = tid; i < M; i += NTHR) {
        unsigned long long mw[NWRD];
        #pragma unroll
        for (int w = 0; w < NWRD; ++w) mw[w] = 0ull;

        float xi1 = s_cor[i][0], yi1 = s_cor[i][1];
        float xi2 = s_cor[i][2], yi2 = s_cor[i][3];
        float ai  = s_area[i];
        float ci  = s_box[i][5];
        for (int j = 0; j < i; ++j) {
            if (s_box[j][5] == ci) {
                float ix1 = fmaxf(xi1, s_cor[j][0]);
                float iy1 = fmaxf(yi1, s_cor[j][1]);
                float ix2 = fminf(xi2, s_cor[j][2]);
                float iy2 = fminf(yi2, s_cor[j][3]);
                float iw = fmaxf(ix2 - ix1, 0.0f);
                float ih = fmaxf(iy2 - iy1, 0.0f);
                float inter = iw * ih;
                float uni   = ai + s_area[j] - inter;
                if (inter / fmaxf(uni, 1e-9f) > 0.3f)
                    mw[j >> 6] |= 1ull << (j & 63);
            }
        }
        #pragma unroll
        for (int w = 0; w < NWRD; ++w) s_sup[i][w] = mw[w];
    }
    __syncthreads();

    // ---- P5: sequential greedy scan on bitmasks (single thread) ----
    if (tid == 0) {
        unsigned long long kw[NWRD];
        #pragma unroll
        for (int w = 0; w < NWRD; ++w) kw[w] = 0ull;
        for (int i = 0; i < M; ++i) {
            unsigned long long hit = 0ull;
            #pragma unroll
            for (int w = 0; w < NWRD; ++w) hit |= (s_sup[i][w] & kw[w]);
            int keep = (hit == 0ull);
            s_keep[i] = keep;
            if (keep) kw[i >> 6] |= 1ull << (i & 63);
        }
    }
    __syncthreads();

    // ---- P6: emit all 300 rows ----
    float* po = out + n * KDET * 7;
    for (int r = tid; r < KDET; r += NTHR) {
        float v0 = 0.f, v1 = 0.f, v2 = 0.f, v3 = 0.f, v4 = 0.f, v5 = 0.f, v6 = 0.f;
        if (r < M && s_keep[r]) {
            v0 = s_box[r][0]; v1 = s_box[r][1]; v2 = s_box[r][2];
            v3 = s_box[r][3]; v4 = s_box[r][4]; v5 = s_box[r][5];
            v6 = (float)n;
        }
        float* pr = po + (long)r * 7;
        pr[0] = v0; pr[1] = v1; pr[2] = v2; pr[3] = v3;
        pr[4] = v4; pr[5] = v5; pr[6] = v6;
    }
}

extern "C" void kernel_launch(void* const* d_in, const int* in_sizes, int n_in,
                              void* d_out, int out_size)
{
    const float* o13 = (const float*)d_in[0];
    const float* o26 = (const float*)d_in[1];
    const float* o52 = (const float*)d_in[2];
    const float* a13 = (const float*)d_in[3];
    const float* a26 = (const float*)d_in[4];
    const float* a52 = (const float*)d_in[5];
    const float* thr = (const float*)d_in[6];

    int N = in_sizes[0] / (255 * HW13);

    detector_fused_kernel<<<N, NTHR>>>(o13, o26, o52, a13, a26, a52, thr,
                                       (float*)d_out);
}